// round 3
// baseline (speedup 1.0000x reference)
#include <cuda_runtime.h>
#include <cuda_bf16.h>
#include <cstdint>

#define NROWS  100000
#define NFEAT  256
#define NOUT   128
#define NEDGES 3200000

// Device-global scratch (allocation APIs forbidden).
__device__ float g_h[(size_t)NROWS * NOUT];          // 51.2 MB projected features
__device__ uint2 g_edge[NEDGES];                     // 25.6 MB row-sorted (col, val) records
__device__ int   g_cnt[NROWS];                       // per-row edge counts
__device__ int   g_off[NROWS + 1];                   // row offsets (CSR-style)
__device__ int   g_cur[NROWS];                       // scatter cursors

// ---------------------------------------------------------------------------
// GEMM: h = x @ W.  128x128 block tile, K-chunks of 16, 8x8 per thread.
// ---------------------------------------------------------------------------
__global__ __launch_bounds__(256, 2)
void gcn_gemm_kernel(const float* __restrict__ x, const float* __restrict__ W) {
    __shared__ float As[16][128];   // [k][row]
    __shared__ float Bs[16][128];   // [k][col]

    const int block_row = blockIdx.x * 128;
    const int t  = threadIdx.x;
    const int tx = t & 15;
    const int ty = t >> 4;

    float acc[8][8];
    #pragma unroll
    for (int i = 0; i < 8; i++)
        #pragma unroll
        for (int j = 0; j < 8; j++)
            acc[i][j] = 0.0f;

    for (int k0 = 0; k0 < NFEAT; k0 += 16) {
        #pragma unroll
        for (int i = 0; i < 2; i++) {
            int idx = t + i * 256;
            int r   = idx >> 2;
            int kk  = (idx & 3) * 4;
            int grow = block_row + r;
            float4 v = make_float4(0.f, 0.f, 0.f, 0.f);
            if (grow < NROWS)
                v = *(const float4*)(x + (size_t)grow * NFEAT + k0 + kk);
            As[kk + 0][r] = v.x;
            As[kk + 1][r] = v.y;
            As[kk + 2][r] = v.z;
            As[kk + 3][r] = v.w;
        }
        #pragma unroll
        for (int i = 0; i < 2; i++) {
            int idx = t + i * 256;
            int kk  = idx >> 5;
            int c   = (idx & 31) * 4;
            float4 v = *(const float4*)(W + (size_t)(k0 + kk) * NOUT + c);
            *(float4*)&Bs[kk][c] = v;
        }
        __syncthreads();

        #pragma unroll
        for (int k = 0; k < 16; k++) {
            float a[8], b[8];
            *(float4*)&a[0] = *(const float4*)&As[k][ty * 8];
            *(float4*)&a[4] = *(const float4*)&As[k][ty * 8 + 4];
            *(float4*)&b[0] = *(const float4*)&Bs[k][tx * 8];
            *(float4*)&b[4] = *(const float4*)&Bs[k][tx * 8 + 4];
            #pragma unroll
            for (int i = 0; i < 8; i++)
                #pragma unroll
                for (int j = 0; j < 8; j++)
                    acc[i][j] += a[i] * b[j];
        }
        __syncthreads();
    }

    #pragma unroll
    for (int i = 0; i < 8; i++) {
        int grow = block_row + ty * 8 + i;
        if (grow < NROWS) {
            float* hp = g_h + (size_t)grow * NOUT + tx * 8;
            *(float4*)(hp + 0) = make_float4(acc[i][0], acc[i][1], acc[i][2], acc[i][3]);
            *(float4*)(hp + 4) = make_float4(acc[i][4], acc[i][5], acc[i][6], acc[i][7]);
        }
    }
}

// ---------------------------------------------------------------------------
// Binning pipeline: zero counts -> histogram -> scan -> scatter
// ---------------------------------------------------------------------------
__global__ void gcn_zero_cnt_kernel() {
    int i = blockIdx.x * blockDim.x + threadIdx.x;
    if (i < NROWS) g_cnt[i] = 0;
}

__global__ __launch_bounds__(256)
void gcn_hist_kernel(const int* __restrict__ er) {
    int stride = gridDim.x * blockDim.x;
    for (int e = blockIdx.x * blockDim.x + threadIdx.x; e < NEDGES; e += stride)
        atomicAdd(&g_cnt[er[e]], 1);
}

// Single-block exclusive scan over 100K counts. 1024 threads x 98 elems each.
__global__ __launch_bounds__(1024)
void gcn_scan_kernel() {
    const int PER = 98;                    // 98 * 1024 = 100352 >= NROWS
    const int t    = threadIdx.x;
    const int lane = t & 31;
    const int wid  = t >> 5;
    const int base = t * PER;

    int s = 0;
    #pragma unroll 4
    for (int i = 0; i < PER; i++) {
        int idx = base + i;
        if (idx < NROWS) s += g_cnt[idx];
    }

    // block-wide exclusive scan of per-thread sums
    __shared__ int warp_tot[32];
    int v = s;
    #pragma unroll
    for (int off = 1; off < 32; off <<= 1) {
        int n = __shfl_up_sync(0xFFFFFFFF, v, off);
        if (lane >= off) v += n;
    }
    if (lane == 31) warp_tot[wid] = v;
    __syncthreads();
    if (wid == 0) {
        int w = warp_tot[lane];
        #pragma unroll
        for (int off = 1; off < 32; off <<= 1) {
            int n = __shfl_up_sync(0xFFFFFFFF, w, off);
            if (lane >= off) w += n;
        }
        warp_tot[lane] = w;
    }
    __syncthreads();
    int running = (v - s) + (wid > 0 ? warp_tot[wid - 1] : 0);

    #pragma unroll 4
    for (int i = 0; i < PER; i++) {
        int idx = base + i;
        if (idx < NROWS) {
            int c = g_cnt[idx];
            g_off[idx] = running;
            g_cur[idx] = running;
            running += c;
        }
    }
    if (t == 0) g_off[NROWS] = NEDGES;
}

__global__ __launch_bounds__(256)
void gcn_scatter_kernel(const float* __restrict__ ev,
                        const int*   __restrict__ er,
                        const int*   __restrict__ ec) {
    int stride = gridDim.x * blockDim.x;
    for (int e = blockIdx.x * blockDim.x + threadIdx.x; e < NEDGES; e += stride) {
        int r = er[e];
        int p = atomicAdd(&g_cur[r], 1);
        g_edge[p] = make_uint2((unsigned)ec[e], __float_as_uint(ev[e]));
    }
}

// ---------------------------------------------------------------------------
// Row reduction: one warp per row. Each lane owns 4 features (float4).
// No atomics: registers accumulate, one plain 512B store per row.
// Empty rows store zeros (replaces the output memset).
// ---------------------------------------------------------------------------
__global__ __launch_bounds__(256)
void gcn_row_kernel(float* __restrict__ out) {
    const int w    = (blockIdx.x * blockDim.x + threadIdx.x) >> 5;
    const int lane = threadIdx.x & 31;
    if (w >= NROWS) return;

    const int s = g_off[w];
    const int e = g_off[w + 1];

    float4 acc = make_float4(0.f, 0.f, 0.f, 0.f);
    for (int i = s; i < e; i++) {
        uint2 rec = __ldg(&g_edge[i]);            // broadcast 8B
        float val = __uint_as_float(rec.y);
        const float4 h4 = *(const float4*)(g_h + (size_t)rec.x * NOUT + lane * 4);
        acc.x += val * h4.x;
        acc.y += val * h4.y;
        acc.z += val * h4.z;
        acc.w += val * h4.w;
    }
    *(float4*)(out + (size_t)w * NOUT + lane * 4) = acc;
}

// ---------------------------------------------------------------------------
// Inputs (metadata order): x [1,100000,256] f32, W [256,128] f32,
// edge_vals [3.2M] f32, edge_rows [3.2M] i32, edge_cols [3.2M] i32.
// Output: [1,100000,128] f32.
// All state (counts/offsets/cursors) rebuilt every call — graph-replay safe.
// ---------------------------------------------------------------------------
extern "C" void kernel_launch(void* const* d_in, const int* in_sizes, int n_in,
                              void* d_out, int out_size) {
    const float* x  = (const float*)d_in[0];
    const float* W  = (const float*)d_in[1];
    const float* ev = (const float*)d_in[2];
    const int*   er = (const int*)d_in[3];
    const int*   ec = (const int*)d_in[4];
    float*       out = (float*)d_out;

    gcn_zero_cnt_kernel<<<(NROWS + 1023) / 1024, 1024>>>();
    gcn_hist_kernel<<<2048, 256>>>(er);
    gcn_scan_kernel<<<1, 1024>>>();
    gcn_scatter_kernel<<<2048, 256>>>(ev, er, ec);

    gcn_gemm_kernel<<<(NROWS + 127) / 128, 256>>>(x, W);

    // one warp per row
    gcn_row_kernel<<<(NROWS * 32 + 255) / 256, 256>>>(out);
}